// round 1
// baseline (speedup 1.0000x reference)
#include <cuda_runtime.h>

#define BB 4
#define CC 384
#define QQ 384
#define HH 256
#define KK 256

#define QT 64
#define HT 16

// Scratch (allocation-free rule: __device__ globals)
__device__ float g_term_h[BB*CC*KK];   // term_h + b1
__device__ float g_term_u[BB*QQ*KK];   // term_u
__device__ float g_whu_t[HH*KK];       // W_hu transposed to [h][k]

// ---------------------------------------------------------------------------
// W_hu transpose: w1 is (K=256 rows, 3H=768 cols) row-major; W_hu[k][h] = w1[k][512+h]
// Store as [h][k] for coalesced main-kernel loads.
__global__ void transpose_whu_kernel(const float* __restrict__ w1) {
    int h = blockIdx.x;      // 0..255
    int k = threadIdx.x;     // 0..255
    g_whu_t[h*KK + k] = w1[(size_t)k*(3*HH) + 2*HH + h];
}

// ---------------------------------------------------------------------------
// term_h / term_u: (rows x H) @ W^T (K x H) -> (rows x K), optional bias.
// One block per row, one thread per k. Each thread streams its own W row (float4).
__global__ void term_kernel(const float* __restrict__ x,
                            const float* __restrict__ w1,
                            const float* __restrict__ b1,
                            float* __restrict__ outbuf,
                            int wcol_off, int use_bias) {
    __shared__ float xrow[HH];
    int r = blockIdx.x;
    int k = threadIdx.x;
    xrow[k] = x[(size_t)r*HH + k];
    __syncthreads();
    float acc = use_bias ? b1[k] : 0.f;
    const float4* wrow = reinterpret_cast<const float4*>(w1 + (size_t)k*(3*HH) + wcol_off);
    #pragma unroll 8
    for (int i = 0; i < HH/4; i++) {
        float4 w = wrow[i];
        acc += xrow[4*i+0]*w.x + xrow[4*i+1]*w.y + xrow[4*i+2]*w.z + xrow[4*i+3]*w.w;
    }
    outbuf[(size_t)r*KK + k] = acc;
}

// ---------------------------------------------------------------------------
// Main kernel: per (b, c, q-tile of 64):
//   S[q,k] = sum_h (h[b,c,h]*u[b,q,h]) * W_hu[k,h]
//   pre1 = S + term_h[b,c,k] + term_u[b,q,k]   (b1 folded into term_h)
//   out[b,c,q] = lrelu( sum_k w2[k]*lrelu(pre1) + b2 )
// 256 threads = 32 k-cols (tx) x 8 q-rows (ty). Micro-tile 8q x 8k per thread.
__global__ __launch_bounds__(256, 2)
void main_kernel(const float* __restrict__ hmat,
                 const float* __restrict__ u,
                 const float* __restrict__ w2,
                 const float* __restrict__ b2,
                 float* __restrict__ out)
{
    __shared__ float h_c[HH];
    __shared__ float th_s[KK];
    __shared__ float w2_s[KK];
    __shared__ float a_s[HT][QT];        // a[h][q] = u * h_c[h]
    __shared__ float w_s[HT][KK];        // W_hu^T tile [h][k]

    const int tx = threadIdx.x;          // 0..31 (k group)
    const int ty = threadIdx.y;          // 0..7  (q group)
    const int t  = ty*32 + tx;           // 0..255
    const int b  = blockIdx.z;
    const int c  = blockIdx.y;
    const int q0 = blockIdx.x * QT;
    const int bc = b*CC + c;

    h_c[t]  = hmat[(size_t)bc*HH + t];
    th_s[t] = g_term_h[(size_t)bc*KK + t];
    w2_s[t] = w2[t];
    __syncthreads();

    float acc[8][8];
    #pragma unroll
    for (int i = 0; i < 8; i++)
        #pragma unroll
        for (int j = 0; j < 8; j++) acc[i][j] = 0.f;

    // tile-load assignments
    const int uq = t >> 2;               // 0..63
    const int uh = (t & 3) * 4;          // 0,4,8,12
    const float* u_base = u + (size_t)(b*QQ + q0 + uq)*HH + uh;
    const int wh = t >> 4;               // 0..15
    const int wk = (t & 15) * 16;        // 0..240

    for (int ht = 0; ht < HH/HT; ht++) {
        // u tile -> a_s (pre-scaled by h_c)
        float4 uv = *reinterpret_cast<const float4*>(u_base + ht*HT);
        a_s[uh+0][uq] = uv.x * h_c[ht*HT + uh + 0];
        a_s[uh+1][uq] = uv.y * h_c[ht*HT + uh + 1];
        a_s[uh+2][uq] = uv.z * h_c[ht*HT + uh + 2];
        a_s[uh+3][uq] = uv.w * h_c[ht*HT + uh + 3];
        // W tile (coalesced from transposed copy)
        const float4* wsrc = reinterpret_cast<const float4*>(g_whu_t + (size_t)(ht*HT + wh)*KK + wk);
        float4* wdst = reinterpret_cast<float4*>(&w_s[wh][wk]);
        #pragma unroll
        for (int j = 0; j < 4; j++) wdst[j] = wsrc[j];
        __syncthreads();

        #pragma unroll
        for (int hh = 0; hh < HT; hh++) {
            float av[8], wv[8];
            *reinterpret_cast<float4*>(av)   = *reinterpret_cast<float4*>(&a_s[hh][ty*8]);     // broadcast
            *reinterpret_cast<float4*>(av+4) = *reinterpret_cast<float4*>(&a_s[hh][ty*8+4]);   // broadcast
            *reinterpret_cast<float4*>(wv)   = *reinterpret_cast<float4*>(&w_s[hh][tx*4]);     // conflict-free
            *reinterpret_cast<float4*>(wv+4) = *reinterpret_cast<float4*>(&w_s[hh][128+tx*4]); // conflict-free
            #pragma unroll
            for (int i = 0; i < 8; i++)
                #pragma unroll
                for (int j = 0; j < 8; j++)
                    acc[i][j] += av[i]*wv[j];
        }
        __syncthreads();
    }

    // epilogue: add terms, lrelu, weighted k-reduction (k-cols are one warp)
    const float b2v = b2[0];
    #pragma unroll
    for (int i = 0; i < 8; i++) {
        const int q = q0 + ty*8 + i;
        const float* tu = g_term_u + (size_t)(b*QQ + q)*KK;
        float4 tuA = *reinterpret_cast<const float4*>(tu + tx*4);
        float4 tuB = *reinterpret_cast<const float4*>(tu + 128 + tx*4);
        float tua[8] = {tuA.x, tuA.y, tuA.z, tuA.w, tuB.x, tuB.y, tuB.z, tuB.w};
        float s = 0.f;
        #pragma unroll
        for (int j = 0; j < 8; j++) {
            const int k = (j < 4) ? (tx*4 + j) : (128 + tx*4 + (j - 4));
            float pre = acc[i][j] + th_s[k] + tua[j];
            pre = fmaxf(pre, 0.f) + 0.01f * fminf(pre, 0.f);   // leaky_relu(0.01)
            s += w2_s[k] * pre;
        }
        #pragma unroll
        for (int off = 16; off; off >>= 1)
            s += __shfl_xor_sync(0xffffffffu, s, off);
        if (tx == 0) {
            float v = s + b2v;
            out[((size_t)b*CC + c)*QQ + q] = fmaxf(v, 0.f) + 0.01f * fminf(v, 0.f);
        }
    }
}

// ---------------------------------------------------------------------------
extern "C" void kernel_launch(void* const* d_in, const int* in_sizes, int n_in,
                              void* d_out, int out_size) {
    (void)in_sizes; (void)n_in; (void)out_size;
    const float* h_  = (const float*)d_in[0];  // (B,C,H)
    const float* u_  = (const float*)d_in[1];  // (B,Q,H)
    const float* w1_ = (const float*)d_in[2];  // (H, 3H)
    const float* b1_ = (const float*)d_in[3];  // (H,)
    const float* w2_ = (const float*)d_in[4];  // (1, H)
    const float* b2_ = (const float*)d_in[5];  // (1,)
    float* out_ = (float*)d_out;               // (B,C,Q)

    float* d_term_h; cudaGetSymbolAddress((void**)&d_term_h, g_term_h);
    float* d_term_u; cudaGetSymbolAddress((void**)&d_term_u, g_term_u);

    transpose_whu_kernel<<<HH, KK>>>(w1_);
    term_kernel<<<BB*CC, KK>>>(h_, w1_, b1_, d_term_h, 0,   1);  // W_h, +b1
    term_kernel<<<BB*QQ, KK>>>(u_, w1_, b1_, d_term_u, HH,  0);  // W_u, no bias

    dim3 grid(QQ/QT, CC, BB);
    dim3 block(32, 8);
    main_kernel<<<grid, block>>>(h_, u_, w2_, b2_, out_);
}

// round 3
// speedup vs baseline: 5.2155x; 5.2155x over previous
#include <cuda_runtime.h>
#include <cstdint>

#define BB 4
#define CC 384
#define QQ 384
#define HH 256
#define KK 256

#define MST 36   // smem row stride (floats) for A/B tiles

// ---------------------------------------------------------------- scratch
__device__ float g_term_h[BB*CC*KK];   // term_h + b1   (exact fp32)
__device__ float g_term_u[BB*QQ*KK];   // term_u        (exact fp32)

__device__ __forceinline__ float tf32r(float x) {   // round-to-nearest tf32
    float y; asm("cvt.rna.tf32.f32 %0, %1;" : "=f"(y) : "f"(x)); return y;
}
__device__ __forceinline__ float lrelu(float x) {
    return fmaxf(x, 0.f) + 0.01f * fminf(x, 0.f);
}
__device__ __forceinline__ void mma8(float* d, const uint32_t* a, uint32_t b0, uint32_t b1) {
    asm volatile("mma.sync.aligned.m16n8k8.row.col.f32.tf32.tf32.f32 "
                 "{%0,%1,%2,%3}, {%4,%5,%6,%7}, {%8,%9}, {%0,%1,%2,%3};"
                 : "+f"(d[0]), "+f"(d[1]), "+f"(d[2]), "+f"(d[3])
                 : "r"(a[0]), "r"(a[1]), "r"(a[2]), "r"(a[3]), "r"(b0), "r"(b1));
}

// ---------------------------------------------------------------- term kernels
// 16 rows per block: each thread k streams its w1 row once, fmas into 16 accs.
__global__ __launch_bounds__(256)
void term16_kernel(const float* __restrict__ x, const float* __restrict__ w1,
                   const float* __restrict__ b1, float* __restrict__ outb,
                   int coloff, int use_bias) {
    __shared__ float xs[16][HH];
    const int k = threadIdx.x;
    const int r0 = blockIdx.x * 16;
    #pragma unroll
    for (int r = 0; r < 16; r++) xs[r][k] = x[(size_t)(r0 + r) * HH + k];
    __syncthreads();
    float acc[16];
    const float bv = use_bias ? b1[k] : 0.f;
    #pragma unroll
    for (int r = 0; r < 16; r++) acc[r] = bv;
    const float4* wr = reinterpret_cast<const float4*>(w1 + (size_t)k * (3 * HH) + coloff);
    for (int i = 0; i < HH / 4; i++) {
        float4 w = wr[i];
        #pragma unroll
        for (int r = 0; r < 16; r++) {
            float4 xv = *reinterpret_cast<const float4*>(&xs[r][4 * i]);
            acc[r] += xv.x * w.x + xv.y * w.y + xv.z * w.z + xv.w * w.w;
        }
    }
    #pragma unroll
    for (int r = 0; r < 16; r++) outb[(size_t)(r0 + r) * KK + k] = acc[r];
}

// ---------------------------------------------------------------- main mma.sync kernel
// Per CTA: (b, c, q-tile 128).  S[q,k] = sum_h (u[b,q,h]*h[b,c,h]) * W_hu[k,h]
// CTA tile M=128 x N=256, K chunks of 32. 8 warps = 2M x 4N, warp tile 64x64.
// Smem layout (floats):
//   As   [128*36]           @ 0
//   Bs   [256*36]           @ 4608
//   red  [4*128]            @ 13824
//   h_c  [256]              @ 14336
//   th_s [256]              @ 14592
//   w2_s [256]              @ 14848       total 15104 floats = 60416 B
#define OFF_AS   0
#define OFF_BS   4608
#define OFF_RED  13824
#define OFF_HC   14336
#define OFF_TH   14592
#define OFF_W2   14848
#define SMEM_FLOATS 15104

__global__ __launch_bounds__(256)
void main_mma_kernel(const float* __restrict__ hmat,
                     const float* __restrict__ u,
                     const float* __restrict__ w1,
                     const float* __restrict__ w2,
                     const float* __restrict__ b2,
                     float* __restrict__ out)
{
    extern __shared__ float sm[];
    float* As   = sm + OFF_AS;
    float* Bs   = sm + OFF_BS;
    float* red  = sm + OFF_RED;
    float* h_c  = sm + OFF_HC;
    float* th_s = sm + OFF_TH;
    float* w2_s = sm + OFF_W2;
    const uint32_t* Asu = reinterpret_cast<const uint32_t*>(As);
    const uint32_t* Bsu = reinterpret_cast<const uint32_t*>(Bs);

    const int tid = threadIdx.x;
    const int lid = tid & 31;
    const int wid = tid >> 5;
    const int g   = lid >> 2;        // group id 0..7
    const int t   = lid & 3;         // thread in group
    const int warpM = wid >> 2;      // 0..1  (64 q-rows each)
    const int warpN = wid & 3;       // 0..3  (64 k-cols each)

    const int b  = blockIdx.z;
    const int c  = blockIdx.y;
    const int q0 = blockIdx.x * 128;
    const int bc = b * CC + c;

    h_c[tid]  = hmat[(size_t)bc * HH + tid];
    th_s[tid] = g_term_h[(size_t)bc * KK + tid];
    w2_s[tid] = w2[tid];
    __syncthreads();

    float acc[4][8][4];
    #pragma unroll
    for (int mt = 0; mt < 4; mt++)
        #pragma unroll
        for (int nt = 0; nt < 8; nt++)
            #pragma unroll
            for (int e = 0; e < 4; e++) acc[mt][nt][e] = 0.f;

    for (int ch = 0; ch < 8; ch++) {
        // ---- A tile: 128 x 32 (u scaled by h_c, tf32) ----
        #pragma unroll
        for (int i = 0; i < 4; i++) {
            const int idx = tid + i * 256;
            const int row = idx >> 3;        // 0..127
            const int c4  = idx & 7;         // 0..7
            const int kb  = ch * 32 + c4 * 4;
            float4 v = *reinterpret_cast<const float4*>(
                u + ((size_t)(b * QQ + q0 + row) * HH + kb));
            float4 hv = *reinterpret_cast<const float4*>(&h_c[kb]);
            v.x = tf32r(v.x * hv.x); v.y = tf32r(v.y * hv.y);
            v.z = tf32r(v.z * hv.z); v.w = tf32r(v.w * hv.w);
            *reinterpret_cast<float4*>(&As[row * MST + c4 * 4]) = v;
        }
        // ---- B tile: 256 x 32 (W_hu rows, tf32) ----
        #pragma unroll
        for (int i = 0; i < 8; i++) {
            const int idx = tid + i * 256;
            const int row = idx >> 3;        // 0..255  (k_out)
            const int c4  = idx & 7;
            float4 v = *reinterpret_cast<const float4*>(
                w1 + ((size_t)row * (3 * HH) + 2 * HH + ch * 32 + c4 * 4));
            v.x = tf32r(v.x); v.y = tf32r(v.y); v.z = tf32r(v.z); v.w = tf32r(v.w);
            *reinterpret_cast<float4*>(&Bs[row * MST + c4 * 4]) = v;
        }
        __syncthreads();

        #pragma unroll
        for (int s = 0; s < 4; s++) {
            const int k0 = s * 8;
            uint32_t af[4][4];
            #pragma unroll
            for (int mt = 0; mt < 4; mt++) {
                const int base = (warpM * 64 + mt * 16 + g) * MST + k0 + t;
                af[mt][0] = Asu[base];
                af[mt][1] = Asu[base + 8 * MST];
                af[mt][2] = Asu[base + 4];
                af[mt][3] = Asu[base + 8 * MST + 4];
            }
            #pragma unroll
            for (int nt = 0; nt < 8; nt++) {
                const int nb = (warpN * 64 + nt * 8 + g) * MST + k0 + t;
                const uint32_t b0 = Bsu[nb];
                const uint32_t b1 = Bsu[nb + 4];
                #pragma unroll
                for (int mt = 0; mt < 4; mt++)
                    mma8(acc[mt][nt], af[mt], b0, b1);
            }
        }
        __syncthreads();
    }

    // ---- epilogue: +term_h +term_u, lrelu, weighted k-reduction ----
    #pragma unroll
    for (int mt = 0; mt < 4; mt++) {
        #pragma unroll
        for (int half = 0; half < 2; half++) {
            const int row = warpM * 64 + mt * 16 + half * 8 + g;
            const int q = q0 + row;
            const float* tu = g_term_u + (size_t)(b * QQ + q) * KK;
            float s = 0.f;
            #pragma unroll
            for (int nt = 0; nt < 8; nt++) {
                const int k = warpN * 64 + nt * 8 + 2 * t;
                float2 tv = *reinterpret_cast<const float2*>(tu + k);
                float v0 = acc[mt][nt][half * 2 + 0] + th_s[k]     + tv.x;
                float v1 = acc[mt][nt][half * 2 + 1] + th_s[k + 1] + tv.y;
                s += w2_s[k]     * lrelu(v0);
                s += w2_s[k + 1] * lrelu(v1);
            }
            s += __shfl_xor_sync(0xffffffffu, s, 1);
            s += __shfl_xor_sync(0xffffffffu, s, 2);
            if (t == 0) red[warpN * 128 + row] = s;
        }
    }
    __syncthreads();
    if (tid < 128) {
        float s = red[tid] + red[128 + tid] + red[256 + tid] + red[384 + tid] + b2[0];
        out[(size_t)bc * QQ + q0 + tid] = lrelu(s);
    }
}

// ---------------------------------------------------------------- launch
extern "C" void kernel_launch(void* const* d_in, const int* in_sizes, int n_in,
                              void* d_out, int out_size) {
    (void)in_sizes; (void)n_in; (void)out_size;
    const float* h_  = (const float*)d_in[0];  // (B,C,H)
    const float* u_  = (const float*)d_in[1];  // (B,Q,H)
    const float* w1_ = (const float*)d_in[2];  // (H, 3H)
    const float* b1_ = (const float*)d_in[3];  // (H,)
    const float* w2_ = (const float*)d_in[4];  // (1, H)
    const float* b2_ = (const float*)d_in[5];  // (1,)
    float* out_ = (float*)d_out;               // (B,C,Q)

    float* d_term_h; cudaGetSymbolAddress((void**)&d_term_h, g_term_h);
    float* d_term_u; cudaGetSymbolAddress((void**)&d_term_u, g_term_u);

    cudaFuncSetAttribute(main_mma_kernel,
                         cudaFuncAttributeMaxDynamicSharedMemorySize,
                         SMEM_FLOATS * (int)sizeof(float));

    term16_kernel<<<BB*CC/16, 256>>>(h_, w1_, b1_, d_term_h, 0,  1);  // W_h (+b1)
    term16_kernel<<<BB*QQ/16, 256>>>(u_, w1_, b1_, d_term_u, HH, 0);  // W_u

    dim3 grid(QQ / 128, CC, BB);
    main_mma_kernel<<<grid, 256, SMEM_FLOATS * sizeof(float)>>>(h_, u_, w1_, w2_, b2_, out_);
}

// round 4
// speedup vs baseline: 5.2914x; 1.0146x over previous
#include <cuda_runtime.h>
#include <cstdint>

#define BB 4
#define CC 384
#define QQ 384
#define HH 256
#define KK 256

#define MST 36   // smem row stride (floats) for A/B tiles

// ---------------------------------------------------------------- scratch
__device__ float g_term_h[BB*CC*KK];   // term_h + b1   (exact fp32)
__device__ float g_term_u[BB*QQ*KK];   // term_u        (exact fp32)
__device__ float g_whu[KK*HH];         // W_hu pre-rounded to tf32, [k][h] dense

__device__ __forceinline__ float tf32r(float x) {   // round-to-nearest tf32
    float y; asm("cvt.rna.tf32.f32 %0, %1;" : "=f"(y) : "f"(x)); return y;
}
__device__ __forceinline__ float lrelu(float x) {
    return fmaxf(x, 0.f) + 0.01f * fminf(x, 0.f);
}
__device__ __forceinline__ void mma8(float* d, const uint32_t* a, uint32_t b0, uint32_t b1) {
    asm volatile("mma.sync.aligned.m16n8k8.row.col.f32.tf32.tf32.f32 "
                 "{%0,%1,%2,%3}, {%4,%5,%6,%7}, {%8,%9}, {%0,%1,%2,%3};"
                 : "+f"(d[0]), "+f"(d[1]), "+f"(d[2]), "+f"(d[3])
                 : "r"(a[0]), "r"(a[1]), "r"(a[2]), "r"(a[3]), "r"(b0), "r"(b1));
}
__device__ __forceinline__ uint32_t smem_u32(const void* p) {
    uint32_t a;
    asm("{ .reg .u64 t; cvta.to.shared.u64 t, %1; cvt.u32.u64 %0, t; }" : "=r"(a) : "l"(p));
    return a;
}
#define CP_ASYNC16(dst, src) \
    asm volatile("cp.async.cg.shared.global [%0], [%1], 16;" :: "r"(dst), "l"(src))
#define CP_COMMIT() asm volatile("cp.async.commit_group;" ::: "memory")
#define CP_WAIT0()  asm volatile("cp.async.wait_group 0;"  ::: "memory")

// ---------------------------------------------------------------- prep: pack W_hu as tf32
__global__ void pack_whu_kernel(const float* __restrict__ w1) {
    const int k = blockIdx.x;      // 0..255
    const int h = threadIdx.x;     // 0..255
    g_whu[k * HH + h] = tf32r(w1[(size_t)k * (3 * HH) + 2 * HH + h]);
}

// ---------------------------------------------------------------- fused term kernel
// blocks [0,96): term_h rows (with b1); blocks [96,192): term_u rows (no bias).
__global__ __launch_bounds__(256)
void term_fused_kernel(const float* __restrict__ h, const float* __restrict__ u,
                       const float* __restrict__ w1, const float* __restrict__ b1) {
    __shared__ float xs[16][HH];
    const int k = threadIdx.x;
    const bool is_h = blockIdx.x < (BB * CC / 16);
    const int r0 = (is_h ? blockIdx.x : blockIdx.x - BB * CC / 16) * 16;
    const float* x = is_h ? h : u;
    float* outb = is_h ? g_term_h : g_term_u;
    const int coloff = is_h ? 0 : HH;

    #pragma unroll
    for (int r = 0; r < 16; r++) xs[r][k] = x[(size_t)(r0 + r) * HH + k];
    __syncthreads();
    float acc[16];
    const float bv = is_h ? b1[k] : 0.f;
    #pragma unroll
    for (int r = 0; r < 16; r++) acc[r] = bv;
    const float4* wr = reinterpret_cast<const float4*>(w1 + (size_t)k * (3 * HH) + coloff);
    for (int i = 0; i < HH / 4; i++) {
        float4 w = wr[i];
        #pragma unroll
        for (int r = 0; r < 16; r++) {
            float4 xv = *reinterpret_cast<const float4*>(&xs[r][4 * i]);
            acc[r] += xv.x * w.x + xv.y * w.y + xv.z * w.z + xv.w * w.w;
        }
    }
    #pragma unroll
    for (int r = 0; r < 16; r++) outb[(size_t)(r0 + r) * KK + k] = acc[r];
}

// ---------------------------------------------------------------- main mma.sync kernel
// Per CTA: (b, c, q-tile 128).  S[q,k] = sum_h (u[b,q,h]*h[b,c,h]) * W_hu[k,h]
// CTA tile M=128 x N=256, K chunks of 32, 2-stage cp.async pipeline.
// 8 warps = 2M x 4N, warp tile 64x64, per-thread 4x8x4 fp32 acc.
// Smem (floats):
//   As[2][128*36] @ 0 / 13824-4608... layout below; Bs cp.async dst 16B-aligned.
#define OFF_AS0  0
#define OFF_BS0  4608
#define OFF_AS1  13824
#define OFF_BS1  18432
#define OFF_RED  27648
#define OFF_HC   28160
#define OFF_TH   28416
#define OFF_W2   28672
#define SMEM_FLOATS 28928

__global__ __launch_bounds__(256, 1)
void main_mma_kernel(const float* __restrict__ hmat,
                     const float* __restrict__ u,
                     const float* __restrict__ w2,
                     const float* __restrict__ b2,
                     float* __restrict__ out)
{
    extern __shared__ float sm[];
    float* As[2]  = { sm + OFF_AS0, sm + OFF_AS1 };
    float* Bs[2]  = { sm + OFF_BS0, sm + OFF_BS1 };
    float* red  = sm + OFF_RED;
    float* h_c  = sm + OFF_HC;
    float* th_s = sm + OFF_TH;
    float* w2_s = sm + OFF_W2;

    const int tid = threadIdx.x;
    const int lid = tid & 31;
    const int wid = tid >> 5;
    const int g   = lid >> 2;        // group 0..7
    const int t   = lid & 3;         // 0..3
    const int warpM = wid >> 2;      // 0..1
    const int warpN = wid & 3;       // 0..3

    const int b  = blockIdx.z;
    const int c  = blockIdx.y;
    const int q0 = blockIdx.x * 128;
    const int bc = b * CC + c;

    h_c[tid]  = hmat[(size_t)bc * HH + tid];
    th_s[tid] = g_term_h[(size_t)bc * KK + tid];
    w2_s[tid] = w2[tid];
    __syncthreads();   // h_c ready for A scaling

    // per-thread tile-load coords (4 A segments, 8 B segments of 16B each)
    const int arow[4] = { (tid) >> 3, (tid + 256) >> 3, (tid + 512) >> 3, (tid + 768) >> 3 };
    const int ac4 = tid & 7;
    const float* u_base = u + (size_t)(b * QQ + q0) * HH;

    float acc[4][8][4];
    #pragma unroll
    for (int mt = 0; mt < 4; mt++)
        #pragma unroll
        for (int nt = 0; nt < 8; nt++)
            #pragma unroll
            for (int e = 0; e < 4; e++) acc[mt][nt][e] = 0.f;

    // ---- helpers as lambdas ----
    auto issue_B = [&](int ch, int buf) {
        const uint32_t bdst = smem_u32(Bs[buf]);
        #pragma unroll
        for (int i = 0; i < 8; i++) {
            const int idx = tid + i * 256;
            const int row = idx >> 3;
            const int c4  = idx & 7;
            CP_ASYNC16(bdst + (row * MST + c4 * 4) * 4,
                       g_whu + (size_t)row * HH + ch * 32 + c4 * 4);
        }
        CP_COMMIT();
    };
    auto load_A = [&](int ch, float4* aN) {
        #pragma unroll
        for (int i = 0; i < 4; i++)
            aN[i] = *reinterpret_cast<const float4*>(
                u_base + (size_t)arow[i] * HH + ch * 32 + ac4 * 4);
    };
    auto store_A = [&](const float4* aN, int buf) {
        const int kb = ac4 * 4;
        #pragma unroll
        for (int i = 0; i < 4; i++) {
            float4 v = aN[i];
            // h_c offset depends on chunk; pass via kb0 below — fold: scaling uses h_c[ch*32+kb+e]
            *reinterpret_cast<float4*>(&As[buf][arow[i] * MST + kb]) = v;
        }
    };

    // prologue: stage 0
    {
        float4 aN[4];
        load_A(0, aN);
        issue_B(0, 0);
        const int kb = ac4 * 4;
        float4 hv = *reinterpret_cast<const float4*>(&h_c[kb]);
        #pragma unroll
        for (int i = 0; i < 4; i++) {
            aN[i].x = tf32r(aN[i].x * hv.x); aN[i].y = tf32r(aN[i].y * hv.y);
            aN[i].z = tf32r(aN[i].z * hv.z); aN[i].w = tf32r(aN[i].w * hv.w);
        }
        store_A(aN, 0);
        CP_WAIT0();
        __syncthreads();
    }

    for (int ch = 0; ch < 8; ch++) {
        const int buf = ch & 1, nbuf = buf ^ 1;
        float4 aN[4];
        if (ch < 7) {
            issue_B(ch + 1, nbuf);
            load_A(ch + 1, aN);
        }

        const uint32_t* Asu = reinterpret_cast<const uint32_t*>(As[buf]);
        const uint32_t* Bsu = reinterpret_cast<const uint32_t*>(Bs[buf]);
        #pragma unroll
        for (int s = 0; s < 4; s++) {
            const int k0 = s * 8;
            uint32_t af[4][4];
            #pragma unroll
            for (int mt = 0; mt < 4; mt++) {
                const int base = (warpM * 64 + mt * 16 + g) * MST + k0 + t;
                af[mt][0] = Asu[base];
                af[mt][1] = Asu[base + 8 * MST];
                af[mt][2] = Asu[base + 4];
                af[mt][3] = Asu[base + 8 * MST + 4];
            }
            #pragma unroll
            for (int nt = 0; nt < 8; nt++) {
                const int nb = (warpN * 64 + nt * 8 + g) * MST + k0 + t;
                const uint32_t b0 = Bsu[nb];
                const uint32_t b1 = Bsu[nb + 4];
                #pragma unroll
                for (int mt = 0; mt < 4; mt++)
                    mma8(acc[mt][nt], af[mt], b0, b1);
            }
        }

        if (ch < 7) {
            const int kb = ac4 * 4;
            float4 hv = *reinterpret_cast<const float4*>(&h_c[(ch + 1) * 32 + kb]);
            #pragma unroll
            for (int i = 0; i < 4; i++) {
                aN[i].x = tf32r(aN[i].x * hv.x); aN[i].y = tf32r(aN[i].y * hv.y);
                aN[i].z = tf32r(aN[i].z * hv.z); aN[i].w = tf32r(aN[i].w * hv.w);
            }
            store_A(aN, nbuf);
            CP_WAIT0();
        }
        __syncthreads();
    }

    // ---- epilogue: +term_h +term_u, lrelu, weighted k-reduction ----
    #pragma unroll
    for (int mt = 0; mt < 4; mt++) {
        #pragma unroll
        for (int half = 0; half < 2; half++) {
            const int row = warpM * 64 + mt * 16 + half * 8 + g;
            const int q = q0 + row;
            const float* tu = g_term_u + (size_t)(b * QQ + q) * KK;
            float s = 0.f;
            #pragma unroll
            for (int nt = 0; nt < 8; nt++) {
                const int k = warpN * 64 + nt * 8 + 2 * t;
                float2 tv = *reinterpret_cast<const float2*>(tu + k);
                float v0 = acc[mt][nt][half * 2 + 0] + th_s[k]     + tv.x;
                float v1 = acc[mt][nt][half * 2 + 1] + th_s[k + 1] + tv.y;
                s += w2_s[k]     * lrelu(v0);
                s += w2_s[k + 1] * lrelu(v1);
            }
            s += __shfl_xor_sync(0xffffffffu, s, 1);
            s += __shfl_xor_sync(0xffffffffu, s, 2);
            if (t == 0) red[warpN * 128 + row] = s;
        }
    }
    __syncthreads();
    if (tid < 128) {
        float s = red[tid] + red[128 + tid] + red[256 + tid] + red[384 + tid] + b2[0];
        out[(size_t)bc * QQ + q0 + tid] = lrelu(s);
    }
}

// ---------------------------------------------------------------- launch
extern "C" void kernel_launch(void* const* d_in, const int* in_sizes, int n_in,
                              void* d_out, int out_size) {
    (void)in_sizes; (void)n_in; (void)out_size;
    const float* h_  = (const float*)d_in[0];  // (B,C,H)
    const float* u_  = (const float*)d_in[1];  // (B,Q,H)
    const float* w1_ = (const float*)d_in[2];  // (H, 3H)
    const float* b1_ = (const float*)d_in[3];  // (H,)
    const float* w2_ = (const float*)d_in[4];  // (1, H)
    const float* b2_ = (const float*)d_in[5];  // (1,)
    float* out_ = (float*)d_out;               // (B,C,Q)

    cudaFuncSetAttribute(main_mma_kernel,
                         cudaFuncAttributeMaxDynamicSharedMemorySize,
                         SMEM_FLOATS * (int)sizeof(float));

    pack_whu_kernel<<<KK, HH>>>(w1_);
    term_fused_kernel<<<BB*CC/16 + BB*QQ/16, 256>>>(h_, u_, w1_, b1_);

    dim3 grid(QQ / 128, CC, BB);
    main_mma_kernel<<<grid, 256, SMEM_FLOATS * sizeof(float)>>>(h_, u_, w2_, b2_, out_);
}

// round 5
// speedup vs baseline: 7.3042x; 1.3804x over previous
#include <cuda_runtime.h>
#include <cuda_fp16.h>
#include <cstdint>

#define BB 4
#define CC 384
#define QQ 384
#define HH 256
#define KK 256

#define ST 40   // smem row stride in halves (80B): banks (20g+t)%32 all distinct

// ---------------------------------------------------------------- scratch
__device__ float g_term_h[BB*CC*KK];                 // term_h + b1 (exact fp32)
__device__ float g_term_u[BB*QQ*KK];                 // term_u     (exact fp32)
__device__ __align__(16) __half g_whu_h[KK*HH];      // W_hu fp16, [k][h] dense

__device__ __forceinline__ float lrelu(float x) {
    return fmaxf(x, 0.f) + 0.01f * fminf(x, 0.f);
}
__device__ __forceinline__ void mma16(float* d, const uint32_t* a, uint32_t b0, uint32_t b1) {
    asm volatile("mma.sync.aligned.m16n8k16.row.col.f32.f16.f16.f32 "
                 "{%0,%1,%2,%3}, {%4,%5,%6,%7}, {%8,%9}, {%0,%1,%2,%3};"
                 : "+f"(d[0]), "+f"(d[1]), "+f"(d[2]), "+f"(d[3])
                 : "r"(a[0]), "r"(a[1]), "r"(a[2]), "r"(a[3]), "r"(b0), "r"(b1));
}
__device__ __forceinline__ uint32_t smem_u32(const void* p) {
    uint32_t a;
    asm("{ .reg .u64 t; cvta.to.shared.u64 t, %1; cvt.u32.u64 %0, t; }" : "=r"(a) : "l"(p));
    return a;
}
#define CP_ASYNC16(dst, src) \
    asm volatile("cp.async.cg.shared.global [%0], [%1], 16;" :: "r"(dst), "l"(src))
#define CP_COMMIT() asm volatile("cp.async.commit_group;" ::: "memory")
#define CP_WAIT0()  asm volatile("cp.async.wait_group 0;"  ::: "memory")

// ---------------------------------------------------------------- prep: pack W_hu fp16
__global__ void pack_whu_kernel(const float* __restrict__ w1) {
    const int k = blockIdx.x;      // 0..255
    const int h = threadIdx.x;     // 0..255
    g_whu_h[k * HH + h] = __float2half_rn(w1[(size_t)k * (3 * HH) + 2 * HH + h]);
}

// ---------------------------------------------------------------- fused term kernel
__global__ __launch_bounds__(256)
void term_fused_kernel(const float* __restrict__ h, const float* __restrict__ u,
                       const float* __restrict__ w1, const float* __restrict__ b1) {
    __shared__ float xs[16][HH];
    const int k = threadIdx.x;
    const bool is_h = blockIdx.x < (BB * CC / 16);
    const int r0 = (is_h ? blockIdx.x : blockIdx.x - BB * CC / 16) * 16;
    const float* x = is_h ? h : u;
    float* outb = is_h ? g_term_h : g_term_u;
    const int coloff = is_h ? 0 : HH;

    #pragma unroll
    for (int r = 0; r < 16; r++) xs[r][k] = x[(size_t)(r0 + r) * HH + k];
    __syncthreads();
    float acc[16];
    const float bv = is_h ? b1[k] : 0.f;
    #pragma unroll
    for (int r = 0; r < 16; r++) acc[r] = bv;
    const float4* wr = reinterpret_cast<const float4*>(w1 + (size_t)k * (3 * HH) + coloff);
    for (int i = 0; i < HH / 4; i++) {
        float4 w = wr[i];
        #pragma unroll
        for (int r = 0; r < 16; r++) {
            float4 xv = *reinterpret_cast<const float4*>(&xs[r][4 * i]);
            acc[r] += xv.x * w.x + xv.y * w.y + xv.z * w.z + xv.w * w.w;
        }
    }
    #pragma unroll
    for (int r = 0; r < 16; r++) outb[(size_t)(r0 + r) * KK + k] = acc[r];
}

// ---------------------------------------------------------------- main fp16 mma kernel
// Per CTA: (b, c, q-tile 128). S[q,k] = sum_h (u[b,q,h]*h[b,c,h]) * W_hu[k,h]
// CTA tile M=128 x N=256, K chunks of 32 (fp16, m16n8k16), 2-stage cp.async pipe.
// 8 warps = 2M x 4N, warp tile 64x64, per-thread 4x8x4 fp32 acc.
// Smem (bytes):
#define AS0  0
#define AS1  10240
#define BS0  20480
#define BS1  40960
#define RED  61440
#define HCO  63488
#define THO  64512
#define W2O  65536
#define SMEM_BYTES 66560

__global__ __launch_bounds__(256, 1)
void main_mma_kernel(const float* __restrict__ hmat,
                     const float* __restrict__ u,
                     const float* __restrict__ w2,
                     const float* __restrict__ b2,
                     float* __restrict__ out)
{
    extern __shared__ char sm[];
    __half* As[2] = { reinterpret_cast<__half*>(sm + AS0), reinterpret_cast<__half*>(sm + AS1) };
    __half* Bs[2] = { reinterpret_cast<__half*>(sm + BS0), reinterpret_cast<__half*>(sm + BS1) };
    float* red  = reinterpret_cast<float*>(sm + RED);
    float* h_c  = reinterpret_cast<float*>(sm + HCO);
    float* th_s = reinterpret_cast<float*>(sm + THO);
    float* w2_s = reinterpret_cast<float*>(sm + W2O);

    const int tid = threadIdx.x;
    const int lid = tid & 31;
    const int wid = tid >> 5;
    const int g   = lid >> 2;        // group 0..7
    const int t   = lid & 3;         // 0..3
    const int warpM = wid >> 2;      // 0..1
    const int warpN = wid & 3;       // 0..3

    const int b  = blockIdx.z;
    const int c  = blockIdx.y;
    const int q0 = blockIdx.x * 128;
    const int bc = b * CC + c;

    h_c[tid]  = hmat[(size_t)bc * HH + tid];
    th_s[tid] = g_term_h[(size_t)bc * KK + tid];
    w2_s[tid] = w2[tid];
    __syncthreads();   // h_c ready

    // A-load coords: 1024 float4-segments (128 rows x 8 c4) over 4 iters
    const int arow[4] = { tid >> 3, (tid + 256) >> 3, (tid + 512) >> 3, (tid + 768) >> 3 };
    const int ac4 = tid & 7;
    const float* u_base = u + (size_t)(b * QQ + q0) * HH;
    // B-load coords: 1024 16B-segments (256 rows x 4 segs) over 4 iters
    const int brow[4] = { tid >> 2, (tid + 256) >> 2, (tid + 512) >> 2, (tid + 768) >> 2 };
    const int bseg = tid & 3;

    float acc[4][8][4];
    #pragma unroll
    for (int mt = 0; mt < 4; mt++)
        #pragma unroll
        for (int nt = 0; nt < 8; nt++)
            #pragma unroll
            for (int e = 0; e < 4; e++) acc[mt][nt][e] = 0.f;

    auto issue_B = [&](int ch, int buf) {
        const uint32_t bdst = smem_u32(Bs[buf]);
        #pragma unroll
        for (int i = 0; i < 4; i++)
            CP_ASYNC16(bdst + brow[i] * (ST * 2) + bseg * 16,
                       g_whu_h + (size_t)brow[i] * HH + ch * 32 + bseg * 8);
        CP_COMMIT();
    };
    auto load_A = [&](int ch, float4* aN) {
        #pragma unroll
        for (int i = 0; i < 4; i++)
            aN[i] = *reinterpret_cast<const float4*>(
                u_base + (size_t)arow[i] * HH + ch * 32 + ac4 * 4);
    };
    auto scale_store_A = [&](int ch, float4* aN, int buf) {
        const int kb = ac4 * 4;
        float4 hv = *reinterpret_cast<const float4*>(&h_c[ch * 32 + kb]);
        #pragma unroll
        for (int i = 0; i < 4; i++) {
            __half2 p0 = __floats2half2_rn(aN[i].x * hv.x, aN[i].y * hv.y);
            __half2 p1 = __floats2half2_rn(aN[i].z * hv.z, aN[i].w * hv.w);
            uint2 pk = { *reinterpret_cast<uint32_t*>(&p0), *reinterpret_cast<uint32_t*>(&p1) };
            *reinterpret_cast<uint2*>(&As[buf][arow[i] * ST + kb]) = pk;
        }
    };

    // prologue
    {
        float4 aN[4];
        load_A(0, aN);
        issue_B(0, 0);
        scale_store_A(0, aN, 0);
        CP_WAIT0();
        __syncthreads();
    }

    for (int ch = 0; ch < 8; ch++) {
        const int buf = ch & 1, nbuf = buf ^ 1;
        float4 aN[4];
        if (ch < 7) {
            issue_B(ch + 1, nbuf);
            load_A(ch + 1, aN);
        }

        const uint32_t* Asu = reinterpret_cast<const uint32_t*>(As[buf]);  // half2 units
        const uint32_t* Bsu = reinterpret_cast<const uint32_t*>(Bs[buf]);
        #pragma unroll
        for (int s = 0; s < 2; s++) {          // two k16 sub-chunks
            const int k2 = s * 8;              // half2 offset
            uint32_t af[4][4];
            #pragma unroll
            for (int mt = 0; mt < 4; mt++) {
                const int r0i = (warpM * 64 + mt * 16 + g) * (ST / 2) + k2 + t;
                af[mt][0] = Asu[r0i];
                af[mt][1] = Asu[r0i + 8 * (ST / 2)];
                af[mt][2] = Asu[r0i + 4];
                af[mt][3] = Asu[r0i + 8 * (ST / 2) + 4];
            }
            #pragma unroll
            for (int nt = 0; nt < 8; nt++) {
                const int nb = (warpN * 64 + nt * 8 + g) * (ST / 2) + k2 + t;
                const uint32_t b0 = Bsu[nb];
                const uint32_t b1 = Bsu[nb + 4];
                #pragma unroll
                for (int mt = 0; mt < 4; mt++)
                    mma16(acc[mt][nt], af[mt], b0, b1);
            }
        }

        if (ch < 7) {
            scale_store_A(ch + 1, aN, nbuf);
            CP_WAIT0();
        }
        __syncthreads();
    }

    // ---- epilogue: +term_h +term_u, lrelu, weighted k-reduction ----
    #pragma unroll
    for (int mt = 0; mt < 4; mt++) {
        #pragma unroll
        for (int half = 0; half < 2; half++) {
            const int row = warpM * 64 + mt * 16 + half * 8 + g;
            const int q = q0 + row;
            const float* tu = g_term_u + (size_t)(b * QQ + q) * KK;
            float s = 0.f;
            #pragma unroll
            for (int nt = 0; nt < 8; nt++) {
                const int k = warpN * 64 + nt * 8 + 2 * t;
                float2 tv = *reinterpret_cast<const float2*>(tu + k);
                float v0 = acc[mt][nt][half * 2 + 0] + th_s[k]     + tv.x;
                float v1 = acc[mt][nt][half * 2 + 1] + th_s[k + 1] + tv.y;
                s += w2_s[k]     * lrelu(v0);
                s += w2_s[k + 1] * lrelu(v1);
            }
            s += __shfl_xor_sync(0xffffffffu, s, 1);
            s += __shfl_xor_sync(0xffffffffu, s, 2);
            if (t == 0) red[warpN * 128 + row] = s;
        }
    }
    __syncthreads();
    if (tid < 128) {
        float s = red[tid] + red[128 + tid] + red[256 + tid] + red[384 + tid] + b2[0];
        out[(size_t)bc * QQ + q0 + tid] = lrelu(s);
    }
}

// ---------------------------------------------------------------- launch
extern "C" void kernel_launch(void* const* d_in, const int* in_sizes, int n_in,
                              void* d_out, int out_size) {
    (void)in_sizes; (void)n_in; (void)out_size;
    const float* h_  = (const float*)d_in[0];  // (B,C,H)
    const float* u_  = (const float*)d_in[1];  // (B,Q,H)
    const float* w1_ = (const float*)d_in[2];  // (H, 3H)
    const float* b1_ = (const float*)d_in[3];  // (H,)
    const float* w2_ = (const float*)d_in[4];  // (1, H)
    const float* b2_ = (const float*)d_in[5];  // (1,)
    float* out_ = (float*)d_out;               // (B,C,Q)

    cudaFuncSetAttribute(main_mma_kernel,
                         cudaFuncAttributeMaxDynamicSharedMemorySize, SMEM_BYTES);

    pack_whu_kernel<<<KK, HH>>>(w1_);
    term_fused_kernel<<<BB*CC/16 + BB*QQ/16, 256>>>(h_, u_, w1_, b1_);

    dim3 grid(QQ / 128, CC, BB);
    main_mma_kernel<<<grid, 256, SMEM_BYTES>>>(h_, u_, w2_, b2_, out_);
}